// round 4
// baseline (speedup 1.0000x reference)
#include <cuda_runtime.h>
#include <cuda_bf16.h>
#include <cstdint>

// ============================================================================
// FirUpsample2D as implicit GEMM on mma.sync (bf16 3-term split, fp32 accum).
// out[n,oc,2*oh+ph,2*ow+pw] = bias[oc] + sum_{c,th,tw} x[n,c,oh-1+th,ow-1+tw]
//                                        * S[p][oc][c][th][tw]
// Per parity p: C[128 oc x 128 pos] += A[128 x 64] * B[64 x 128] over 36 chunks.
// ============================================================================

#define CIN 256
#define OCH 256

// split weights, row-major [p*2+half][kc=36][m=128][k=64] bf16
__device__ __align__(16) unsigned char g_Wh[8 * 36 * 16384];
__device__ __align__(16) unsigned char g_Wl[8 * 36 * 16384];
// split input, packed c-pairs: word[(n*128+c2)*4096 + h*64 + w] = (bf16(c=2*c2), bf16(c=2*c2+1))
__device__ __align__(16) uint32_t g_Xh[8 * 128 * 4096];
__device__ __align__(16) uint32_t g_Xl[8 * 128 * 4096];

__device__ __forceinline__ uint32_t swz(uint32_t o) { return o ^ ((o >> 3) & 0x70); }

__device__ __forceinline__ uint32_t smem_u32(const void* p) {
    uint32_t a;
    asm("{ .reg .u64 t; cvta.to.shared.u64 t, %1; cvt.u32.u64 %0, t; }" : "=r"(a) : "l"(p));
    return a;
}

#define CP16(d, s) asm volatile("cp.async.cg.shared.global [%0], [%1], 16;" :: "r"(d), "l"(s) : "memory")
#define CP4Z(d, s, z) asm volatile("cp.async.ca.shared.global [%0], [%1], 4, %2;" :: "r"(d), "l"(s), "r"(z) : "memory")
#define CP_COMMIT() asm volatile("cp.async.commit_group;" ::: "memory")
#define CP_WAIT1() asm volatile("cp.async.wait_group 1;" ::: "memory")
#define CP_WAIT0() asm volatile("cp.async.wait_group 0;" ::: "memory")

#define LDSM4(r, a) asm volatile( \
    "ldmatrix.sync.aligned.m8n8.x4.shared.b16 {%0,%1,%2,%3}, [%4];" \
    : "=r"((r)[0]), "=r"((r)[1]), "=r"((r)[2]), "=r"((r)[3]) : "r"(a))
#define LDSM2(r, a) asm volatile( \
    "ldmatrix.sync.aligned.m8n8.x2.shared.b16 {%0,%1}, [%2];" \
    : "=r"((r)[0]), "=r"((r)[1]) : "r"(a))

#define MMA(c, a, b) asm volatile( \
    "mma.sync.aligned.m16n8k16.row.col.f32.bf16.bf16.f32 " \
    "{%0,%1,%2,%3},{%4,%5,%6,%7},{%8,%9},{%0,%1,%2,%3};" \
    : "+f"((c)[0]), "+f"((c)[1]), "+f"((c)[2]), "+f"((c)[3]) \
    : "r"((a)[0]), "r"((a)[1]), "r"((a)[2]), "r"((a)[3]), "r"((b)[0]), "r"((b)[1]))

// ---------------------------------------------------------------------------
// prep 1: Weff = conv-weight composed with FIR quarter-kernel, split h/l bf16
// grid <<<256,256>>>: blockIdx.x = oc, tid = c
// ---------------------------------------------------------------------------
__global__ void prep_weff_kernel(const float* __restrict__ weight) {
    int oc = blockIdx.x;
    int c  = threadIdx.x;
    const float kq[4] = {0.25f, 0.75f, 0.75f, 0.25f};

    float w[3][3];
#pragma unroll
    for (int uh = 0; uh < 3; uh++)
#pragma unroll
        for (int uw = 0; uw < 3; uw++)
            w[uh][uw] = weight[((oc * CIN + c) * 3 + uh) * 3 + uw];

    float Keff[6][6];
#pragma unroll
    for (int a = 0; a < 6; a++)
#pragma unroll
        for (int b = 0; b < 6; b++) Keff[a][b] = 0.0f;
#pragma unroll
    for (int uh = 0; uh < 3; uh++)
#pragma unroll
        for (int uw = 0; uw < 3; uw++) {
            float wv = w[uh][uw];
#pragma unroll
            for (int vh = 0; vh < 4; vh++)
#pragma unroll
                for (int vw = 0; vw < 4; vw++)
                    Keff[uh + vh][uw + vw] += wv * kq[vh] * kq[vw];
        }

    int half = oc >> 7, m = oc & 127;
    int kin = c & 63;
#pragma unroll
    for (int p = 0; p < 4; p++) {
        int ph = p >> 1, pw = p & 1;
#pragma unroll
        for (int th = 0; th < 3; th++)
#pragma unroll
            for (int tw = 0; tw < 3; tw++) {
                float v = Keff[2 * th + 1 - ph][2 * tw + 1 - pw];
                __nv_bfloat16 vh = __float2bfloat16(v);
                __nv_bfloat16 vl = __float2bfloat16(v - __bfloat162float(vh));
                int kc = (th * 3 + tw) * 4 + (c >> 6);
                uint32_t off = (uint32_t)((p * 2 + half) * 36 + kc) * 16384u
                             + (uint32_t)m * 128u + (uint32_t)kin * 2u;
                *(__nv_bfloat16*)(g_Wh + off) = vh;
                *(__nv_bfloat16*)(g_Wl + off) = vl;
            }
    }
}

// ---------------------------------------------------------------------------
// prep 2: x fp32 -> packed bf16 h/l c-pair words
// ---------------------------------------------------------------------------
__global__ void prep_x_kernel(const float* __restrict__ x) {
    int idx = blockIdx.x * blockDim.x + threadIdx.x;   // 0 .. 8*128*4096-1
    int hw = idx & 4095;
    int c2 = (idx >> 12) & 127;
    int n  = idx >> 19;
    const float* px = x + ((size_t)n * CIN + 2 * c2) * 4096 + hw;
    float v0 = px[0], v1 = px[4096];
    __nv_bfloat16 h0 = __float2bfloat16(v0);
    __nv_bfloat16 h1 = __float2bfloat16(v1);
    __nv_bfloat16 l0 = __float2bfloat16(v0 - __bfloat162float(h0));
    __nv_bfloat16 l1 = __float2bfloat16(v1 - __bfloat162float(h1));
    g_Xh[idx] = (uint32_t)__bfloat16_as_ushort(h0) | ((uint32_t)__bfloat16_as_ushort(h1) << 16);
    g_Xl[idx] = (uint32_t)__bfloat16_as_ushort(l0) | ((uint32_t)__bfloat16_as_ushort(l1) << 16);
}

// ---------------------------------------------------------------------------
// main: grid (256, 2 oc-halves, 4 parities), 512 threads, 128KB dyn smem
// stage s (64KB): Ah @+0, Al @+16K, Bh @+32K, Bl @+48K (all SW128-swizzled)
// warp w: tile m [wm*32, +32) x n [wn*32, +32), wm=w&3, wn=w>>2
// ---------------------------------------------------------------------------
__global__ __launch_bounds__(512, 1) void conv_mma_kernel(
    const float* __restrict__ bias, float* __restrict__ out)
{
    extern __shared__ char smem[];
    const uint32_t sb = smem_u32(smem);
    const int tid = threadIdx.x;
    const int warp = tid >> 5, lane = tid & 31;

    const int bx = blockIdx.x;
    const int n = bx >> 5, t = bx & 31;
    const int ih0 = (t >> 2) * 8, iw0 = (t & 3) * 16;
    const int ochalf = blockIdx.y;
    const int p = blockIdx.z;
    const int ph = p >> 1, pw = p & 1;

    const int wm = warp & 3, wn = warp >> 2;

    float acc[2][4][4];
#pragma unroll
    for (int mf = 0; mf < 2; mf++)
#pragma unroll
        for (int nf = 0; nf < 4; nf++)
#pragma unroll
            for (int i = 0; i < 4; i++) acc[mf][nf][i] = 0.0f;

    // --- per-thread B prefetch geometry
    const int cw = tid & 15, rest = tid >> 4;
    const int rB = rest & 7, cg = rest >> 3;     // cg 0..3: 8 c-pairs each

    // --- per-thread ldmatrix geometry
    const int rowA0 = wm * 32 + (lane & 7) + ((lane >> 3) & 1) * 8;
    const int kbA = ((lane >> 4) & 1) * 16;
    const int rowB0 = wn * 32 + (lane & 7);
    const int kbB = ((lane >> 3) & 1) * 16;

    const unsigned char* wbh = g_Wh + (size_t)((p * 2 + ochalf) * 36) * 16384;
    const unsigned char* wbl = g_Wl + (size_t)((p * 2 + ochalf) * 36) * 16384;

#define PREFETCH(kc, s) do {                                                        \
    const unsigned char* srcH = wbh + (size_t)(kc) * 16384;                         \
    const unsigned char* srcL = wbl + (size_t)(kc) * 16384;                         \
    uint32_t stg = sb + (uint32_t)(s) * 65536u;                                     \
    _Pragma("unroll")                                                               \
    for (int i = 0; i < 2; i++) {                                                   \
        uint32_t v = (uint32_t)(i * 512 + tid) * 16u;                               \
        CP16(stg + swz(v), srcH + v);                                               \
        CP16(stg + 16384u + swz(v), srcL + v);                                      \
    }                                                                               \
    {                                                                               \
        int tap = (kc) >> 2;                                                        \
        int th = tap / 3, tw = tap - th * 3;                                        \
        int cpb = ((kc) & 3) * 32;                                                  \
        int gh = ih0 + rB - 1 + th, gw = iw0 + cw - 1 + tw;                         \
        int inb = ((unsigned)gh < 64u && (unsigned)gw < 64u) ? 4 : 0;               \
        uint32_t gidx = (uint32_t)((n * 128 + cpb) * 4096)                          \
                        + (inb ? (uint32_t)(gh * 64 + gw) : 0u);                    \
        uint32_t brow = (uint32_t)(rB * 16 + cw) * 128u;                            \
        _Pragma("unroll")                                                           \
        for (int i = 0; i < 8; i++) {                                               \
            int c2 = cg * 8 + i;                                                    \
            uint32_t doff = swz(brow + (uint32_t)c2 * 4u);                          \
            CP4Z(stg + 32768u + doff, g_Xh + gidx + c2 * 4096, inb);                \
            CP4Z(stg + 49152u + doff, g_Xl + gidx + c2 * 4096, inb);                \
        }                                                                           \
    }                                                                               \
} while (0)

    PREFETCH(0, 0);
    CP_COMMIT();

    for (int kc = 0; kc < 36; kc++) {
        const int s = kc & 1;
        if (kc + 1 < 36) {
            PREFETCH(kc + 1, s ^ 1);
            CP_COMMIT();
            CP_WAIT1();
        } else {
            CP_WAIT0();
        }
        __syncthreads();

        const uint32_t A0 = sb + (uint32_t)s * 65536u;
        const uint32_t A1 = A0 + 16384u;
        const uint32_t B0 = A0 + 32768u;
        const uint32_t B1 = A0 + 49152u;

#pragma unroll
        for (int ks = 0; ks < 4; ks++) {
            uint32_t ah[2][4], al[2][4], bh[4][2], bl[4][2];
#pragma unroll
            for (int mf = 0; mf < 2; mf++) {
                uint32_t ao = swz((uint32_t)(rowA0 + mf * 16) * 128u + (uint32_t)(ks * 32 + kbA));
                LDSM4(ah[mf], A0 + ao);
                LDSM4(al[mf], A1 + ao);
            }
#pragma unroll
            for (int nf = 0; nf < 4; nf++) {
                uint32_t bo = swz((uint32_t)(rowB0 + nf * 8) * 128u + (uint32_t)(ks * 32 + kbB));
                LDSM2(bh[nf], B0 + bo);
                LDSM2(bl[nf], B1 + bo);
            }
#pragma unroll
            for (int mf = 0; mf < 2; mf++)
#pragma unroll
                for (int nf = 0; nf < 4; nf++) {
                    MMA(acc[mf][nf], ah[mf], bh[nf]);
                    MMA(acc[mf][nf], al[mf], bh[nf]);
                    MMA(acc[mf][nf], ah[mf], bl[nf]);
                }
        }
        __syncthreads();
    }

    // ---- epilogue: accums -> smem [oc][pos] (pitch 132), then coalesced out
    float* ep = (float*)smem;
    {
        int g = lane >> 2, tq = lane & 3;
#pragma unroll
        for (int mf = 0; mf < 2; mf++)
#pragma unroll
            for (int nf = 0; nf < 4; nf++) {
                int row = wm * 32 + mf * 16 + g;
                int col = wn * 32 + nf * 8 + tq * 2;
                ep[row * 132 + col]           = acc[mf][nf][0];
                ep[row * 132 + col + 1]       = acc[mf][nf][1];
                ep[(row + 8) * 132 + col]     = acc[mf][nf][2];
                ep[(row + 8) * 132 + col + 1] = acc[mf][nf][3];
            }
    }
    __syncthreads();

    for (int e = tid; e < 16384; e += 512) {
        int ocl = e >> 7, posi = e & 127;
        int r = posi >> 4, c = posi & 15;
        int oc = ochalf * 128 + ocl;
        float v = ep[ocl * 132 + posi] + bias[oc];
        out[(((size_t)n * OCH + oc) * 128 + 2 * (ih0 + r) + ph) * 128
            + 2 * (iw0 + c) + pw] = v;
    }
}

extern "C" void kernel_launch(void* const* d_in, const int* in_sizes, int n_in,
                              void* d_out, int out_size) {
    const float* hidden = (const float*)d_in[0];   // (8,256,64,64)
    const float* weight = (const float*)d_in[1];   // (256,256,3,3)
    const float* bias   = (const float*)d_in[2];   // (256,)
    float* out = (float*)d_out;                    // (8,256,128,128)

    cudaFuncSetAttribute(conv_mma_kernel,
                         cudaFuncAttributeMaxDynamicSharedMemorySize, 131072);

    prep_weff_kernel<<<256, 256>>>(weight);
    prep_x_kernel<<<8192, 512>>>(hidden);
    conv_mma_kernel<<<dim3(256, 2, 4), 512, 131072>>>(bias, out);
}

// round 5
// speedup vs baseline: 2.6531x; 2.6531x over previous
#include <cuda_runtime.h>
#include <cuda_fp16.h>
#include <cstdint>

// ============================================================================
// FirUpsample2D as implicit GEMM on mma.sync, single-pass fp16, fp32 accum.
// out[n,oc,2*oh+ph,2*ow+pw] = bias[oc] + sum_{c,th,tw} x[n,c,oh-1+th,ow-1+tw]
//                                        * S[p][oc][c][th][tw]
// Key fact: the im2col B tile is identical for all 4 parities; only A differs.
// CTA: C[256 M x 128 N], M = (pw in {0,1}) x 128 oc, N = 128 positions,
// K = 2304 in 36 chunks of 64.
// ============================================================================

#define CIN 256
#define OCH 256

// fp16 weights, row-major [(p*2+half)][kc=36][m=128][k=64]
__device__ __align__(16) unsigned char g_W[8 * 36 * 16384];
// fp16 input, packed c-pairs: word[(n*128+c2)*4096 + h*64 + w] = (fp16 c=2c2, fp16 c=2c2+1)
__device__ __align__(16) uint32_t g_Xp[8 * 128 * 4096];

__device__ __forceinline__ uint32_t swz(uint32_t o) { return o ^ ((o >> 3) & 0x70); }

__device__ __forceinline__ uint32_t smem_u32(const void* p) {
    uint32_t a;
    asm("{ .reg .u64 t; cvta.to.shared.u64 t, %1; cvt.u32.u64 %0, t; }" : "=r"(a) : "l"(p));
    return a;
}

#define CP16(d, s) asm volatile("cp.async.cg.shared.global [%0], [%1], 16;" :: "r"(d), "l"(s) : "memory")
#define CP4Z(d, s, z) asm volatile("cp.async.ca.shared.global [%0], [%1], 4, %2;" :: "r"(d), "l"(s), "r"(z) : "memory")
#define CP_COMMIT() asm volatile("cp.async.commit_group;" ::: "memory")
#define CP_WAIT1() asm volatile("cp.async.wait_group 1;" ::: "memory")
#define CP_WAIT0() asm volatile("cp.async.wait_group 0;" ::: "memory")

#define LDSM4(r, a) asm volatile( \
    "ldmatrix.sync.aligned.m8n8.x4.shared.b16 {%0,%1,%2,%3}, [%4];" \
    : "=r"((r)[0]), "=r"((r)[1]), "=r"((r)[2]), "=r"((r)[3]) : "r"(a))
#define LDSM2(r, a) asm volatile( \
    "ldmatrix.sync.aligned.m8n8.x2.shared.b16 {%0,%1}, [%2];" \
    : "=r"((r)[0]), "=r"((r)[1]) : "r"(a))

#define MMA(c, a, b) asm volatile( \
    "mma.sync.aligned.m16n8k16.row.col.f32.f16.f16.f32 " \
    "{%0,%1,%2,%3},{%4,%5,%6,%7},{%8,%9},{%0,%1,%2,%3};" \
    : "+f"((c)[0]), "+f"((c)[1]), "+f"((c)[2]), "+f"((c)[3]) \
    : "r"((a)[0]), "r"((a)[1]), "r"((a)[2]), "r"((a)[3]), "r"((b)[0]), "r"((b)[1]))

// ---------------------------------------------------------------------------
// prep 1: Weff = conv weight composed with FIR quarter-kernel -> fp16 images
// grid <<<256,256>>>: blockIdx.x = oc, tid = c
// ---------------------------------------------------------------------------
__global__ void prep_weff_kernel(const float* __restrict__ weight) {
    int oc = blockIdx.x;
    int c  = threadIdx.x;
    const float kq[4] = {0.25f, 0.75f, 0.75f, 0.25f};

    float w[3][3];
#pragma unroll
    for (int uh = 0; uh < 3; uh++)
#pragma unroll
        for (int uw = 0; uw < 3; uw++)
            w[uh][uw] = weight[((oc * CIN + c) * 3 + uh) * 3 + uw];

    float Keff[6][6];
#pragma unroll
    for (int a = 0; a < 6; a++)
#pragma unroll
        for (int b = 0; b < 6; b++) Keff[a][b] = 0.0f;
#pragma unroll
    for (int uh = 0; uh < 3; uh++)
#pragma unroll
        for (int uw = 0; uw < 3; uw++) {
            float wv = w[uh][uw];
#pragma unroll
            for (int vh = 0; vh < 4; vh++)
#pragma unroll
                for (int vw = 0; vw < 4; vw++)
                    Keff[uh + vh][uw + vw] += wv * kq[vh] * kq[vw];
        }

    int half = oc >> 7, m = oc & 127;
    int kin = c & 63;
#pragma unroll
    for (int p = 0; p < 4; p++) {
        int ph = p >> 1, pw = p & 1;
#pragma unroll
        for (int th = 0; th < 3; th++)
#pragma unroll
            for (int tw = 0; tw < 3; tw++) {
                float v = Keff[2 * th + 1 - ph][2 * tw + 1 - pw];
                int kc = (th * 3 + tw) * 4 + (c >> 6);
                uint32_t off = (uint32_t)((p * 2 + half) * 36 + kc) * 16384u
                             + (uint32_t)m * 128u + (uint32_t)kin * 2u;
                *(__half*)(g_W + off) = __float2half_rn(v);
            }
    }
}

// ---------------------------------------------------------------------------
// prep 2: x fp32 -> packed fp16 c-pair words
// ---------------------------------------------------------------------------
__global__ void prep_x_kernel(const float* __restrict__ x) {
    int idx = blockIdx.x * blockDim.x + threadIdx.x;   // 0 .. 8*128*4096-1
    int hw = idx & 4095;
    int c2 = (idx >> 12) & 127;
    int n  = idx >> 19;
    const float* px = x + ((size_t)n * CIN + 2 * c2) * 4096 + hw;
    __half h0 = __float2half_rn(px[0]);
    __half h1 = __float2half_rn(px[4096]);
    g_Xp[idx] = (uint32_t)__half_as_ushort(h0) | ((uint32_t)__half_as_ushort(h1) << 16);
}

// ---------------------------------------------------------------------------
// main: grid (256 pos-tiles, 2 oc-halves, 2 ph), 512 threads, 96KB dyn smem
// stage s (48KB): A (2 pw tiles, 32KB, rows 0..255) @ +0, B (16KB) @ +32K
// warp tile: M=64 x N=32.  wm = warp&3 (M), wn = warp>>2 (N).
// ---------------------------------------------------------------------------
__global__ __launch_bounds__(512, 1) void conv_mma_kernel(
    const float* __restrict__ bias, float* __restrict__ out)
{
    extern __shared__ char smem[];
    const uint32_t sb = smem_u32(smem);
    const int tid = threadIdx.x;
    const int warp = tid >> 5, lane = tid & 31;

    const int bx = blockIdx.x;
    const int n = bx >> 5, t = bx & 31;
    const int ih0 = (t >> 2) * 8, iw0 = (t & 3) * 16;
    const int ochalf = blockIdx.y;
    const int ph = blockIdx.z;

    const int wm = warp & 3, wn = warp >> 2;

    float acc[4][4][4];
#pragma unroll
    for (int mf = 0; mf < 4; mf++)
#pragma unroll
        for (int nf = 0; nf < 4; nf++)
#pragma unroll
            for (int i = 0; i < 4; i++) acc[mf][nf][i] = 0.0f;

    // --- B prefetch geometry: thread -> (pos row rB, pos col cw, 8 c-pairs)
    const int cw = tid & 15, rest = tid >> 4;
    const int rB = rest & 7, cg = rest >> 3;

    // --- ldmatrix geometry (identical mapping to the validated R4 kernel)
    const int rowA0 = wm * 64 + (lane & 7) + ((lane >> 3) & 1) * 8;
    const int kbA = ((lane >> 4) & 1) * 16;
    const int rowB0 = wn * 32 + (lane & 7);
    const int kbB = ((lane >> 3) & 1) * 16;

#define PREFETCH(kc, s) do {                                                        \
    uint32_t stg = sb + (uint32_t)(s) * 49152u;                                     \
    _Pragma("unroll")                                                               \
    for (int pslot = 0; pslot < 2; pslot++) {                                       \
        const unsigned char* src = g_W +                                            \
            (size_t)(((ph * 2 + pslot) * 2 + ochalf) * 36 + (kc)) * 16384u;         \
        _Pragma("unroll")                                                           \
        for (int i = 0; i < 2; i++) {                                               \
            uint32_t v = (uint32_t)(i * 512 + tid) * 16u;                           \
            CP16(stg + pslot * 16384u + swz(v), src + v);                           \
        }                                                                           \
    }                                                                               \
    {                                                                               \
        int tap = (kc) >> 2;                                                        \
        int th = tap / 3, tw = tap - th * 3;                                        \
        int cpb = ((kc) & 3) * 32;                                                  \
        int gh = ih0 + rB - 1 + th, gw = iw0 + cw - 1 + tw;                         \
        int inb = ((unsigned)gh < 64u && (unsigned)gw < 64u) ? 4 : 0;               \
        uint32_t gidx = (uint32_t)((n * 128 + cpb) * 4096)                          \
                        + (inb ? (uint32_t)(gh * 64 + gw) : 0u);                    \
        uint32_t brow = (uint32_t)(rB * 16 + cw) * 128u;                            \
        _Pragma("unroll")                                                           \
        for (int i = 0; i < 8; i++) {                                               \
            int c2 = cg * 8 + i;                                                    \
            CP4Z(stg + 32768u + swz(brow + (uint32_t)c2 * 4u),                      \
                 g_Xp + gidx + c2 * 4096, inb);                                     \
        }                                                                           \
    }                                                                               \
} while (0)

    PREFETCH(0, 0);
    CP_COMMIT();

    for (int kc = 0; kc < 36; kc++) {
        const int s = kc & 1;
        if (kc + 1 < 36) {
            PREFETCH(kc + 1, s ^ 1);
            CP_COMMIT();
            CP_WAIT1();
        } else {
            CP_WAIT0();
        }
        __syncthreads();

        const uint32_t A0 = sb + (uint32_t)s * 49152u;
        const uint32_t B0 = A0 + 32768u;

#pragma unroll
        for (int ks = 0; ks < 4; ks++) {
            uint32_t a[4][4], b[4][2];
#pragma unroll
            for (int mf = 0; mf < 4; mf++) {
                uint32_t ao = swz((uint32_t)(rowA0 + mf * 16) * 128u
                                  + (uint32_t)(ks * 32 + kbA));
                LDSM4(a[mf], A0 + ao);
            }
#pragma unroll
            for (int nf = 0; nf < 4; nf++) {
                uint32_t bo = swz((uint32_t)(rowB0 + nf * 8) * 128u
                                  + (uint32_t)(ks * 32 + kbB));
                LDSM2(b[nf], B0 + bo);
            }
#pragma unroll
            for (int mf = 0; mf < 4; mf++)
#pragma unroll
                for (int nf = 0; nf < 4; nf++)
                    MMA(acc[mf][nf], a[mf], b[nf]);
        }
        __syncthreads();
    }

    // ---- epilogue: two passes over oc-quarters; ep[pslot][ocq 0..63][pos 128]
    float* ep = (float*)smem;                     // pitch 130 floats
    const int g = lane >> 2, tq = lane & 3;
    const int ocq_t = tid >> 3, r_t = tid & 7;

#pragma unroll
    for (int q = 0; q < 2; q++) {
        __syncthreads();
        if ((wm & 1) == q) {
            int pslot = wm >> 1;
#pragma unroll
            for (int mf = 0; mf < 4; mf++) {
                int ocq = mf * 16 + g;
#pragma unroll
                for (int nf = 0; nf < 4; nf++) {
                    int col = wn * 32 + nf * 8 + tq * 2;
                    float* e = ep + (pslot * 64 + ocq) * 130 + col;
                    *(float2*)e         = make_float2(acc[mf][nf][0], acc[mf][nf][1]);
                    *(float2*)(e + 8 * 130) = make_float2(acc[mf][nf][2], acc[mf][nf][3]);
                }
            }
        }
        __syncthreads();

        int oc = ochalf * 128 + q * 64 + ocq_t;
        float bv = bias[oc];
        const float* e0 = ep + ocq_t * 130 + r_t * 16;
        const float* e1 = e0 + 64 * 130;
        float4* dst = (float4*)(out + (((size_t)n * OCH + oc) * 128
                        + 2 * (ih0 + r_t) + ph) * 128 + 2 * iw0);
#pragma unroll
        for (int k = 0; k < 8; k++) {
            float4 v;
            v.x = e0[2 * k] + bv;
            v.y = e1[2 * k] + bv;
            v.z = e0[2 * k + 1] + bv;
            v.w = e1[2 * k + 1] + bv;
            dst[k] = v;
        }
    }
}

extern "C" void kernel_launch(void* const* d_in, const int* in_sizes, int n_in,
                              void* d_out, int out_size) {
    const float* hidden = (const float*)d_in[0];   // (8,256,64,64)
    const float* weight = (const float*)d_in[1];   // (256,256,3,3)
    const float* bias   = (const float*)d_in[2];   // (256,)
    float* out = (float*)d_out;                    // (8,256,128,128)

    cudaFuncSetAttribute(conv_mma_kernel,
                         cudaFuncAttributeMaxDynamicSharedMemorySize, 98304);

    prep_weff_kernel<<<256, 256>>>(weight);
    prep_x_kernel<<<8192, 512>>>(hidden);
    conv_mma_kernel<<<dim3(256, 2, 2), 512, 98304>>>(bias, out);
}

// round 6
// speedup vs baseline: 2.7652x; 1.0422x over previous
#include <cuda_runtime.h>
#include <cuda_fp16.h>
#include <cstdint>

// ============================================================================
// FirUpsample2D as implicit GEMM on mma.sync, single-pass fp16, fp32 accum.
// out[n,oc,2*oh+ph,2*ow+pw] = bias[oc] + sum_{c,th,tw} x[n,c,oh-1+th,ow-1+tw]
//                                        * S[p][oc][c][th][tw]
// CTA: C[256 M x 128 N], M = (pw in {0,1}) x 128 oc, N = 128 positions.
// K = 2304 in 18 pipeline stages of 128 (2 x 64-chunk, same FIR tap).
// ============================================================================

#define CIN 256
#define OCH 256

// fp16 weights, row-major [(p*2+half)][kc=36][m=128][k=64] (16KB units)
__device__ __align__(16) unsigned char g_W[8 * 36 * 16384];
// fp16 input, c8-packed: uint4[(n*32 + c8)*4096 + h*64 + w] = 8 halves, ch 8*c8..8*c8+7
__device__ __align__(16) uint4 g_X8[8 * 32 * 4096];

__device__ __forceinline__ uint32_t swz(uint32_t o) { return o ^ ((o >> 3) & 0x70); }

__device__ __forceinline__ uint32_t smem_u32(const void* p) {
    uint32_t a;
    asm("{ .reg .u64 t; cvta.to.shared.u64 t, %1; cvt.u32.u64 %0, t; }" : "=r"(a) : "l"(p));
    return a;
}

#define CP16(d, s) asm volatile("cp.async.cg.shared.global [%0], [%1], 16;" :: "r"(d), "l"(s) : "memory")
#define CP16Z(d, s, z) asm volatile("cp.async.cg.shared.global [%0], [%1], 16, %2;" :: "r"(d), "l"(s), "r"(z) : "memory")
#define CP_COMMIT() asm volatile("cp.async.commit_group;" ::: "memory")
#define CP_WAIT1() asm volatile("cp.async.wait_group 1;" ::: "memory")
#define CP_WAIT0() asm volatile("cp.async.wait_group 0;" ::: "memory")

#define LDSM4(r, a) asm volatile( \
    "ldmatrix.sync.aligned.m8n8.x4.shared.b16 {%0,%1,%2,%3}, [%4];" \
    : "=r"((r)[0]), "=r"((r)[1]), "=r"((r)[2]), "=r"((r)[3]) : "r"(a))
#define LDSM2(r, a) asm volatile( \
    "ldmatrix.sync.aligned.m8n8.x2.shared.b16 {%0,%1}, [%2];" \
    : "=r"((r)[0]), "=r"((r)[1]) : "r"(a))

#define MMA(c, a, b) asm volatile( \
    "mma.sync.aligned.m16n8k16.row.col.f32.f16.f16.f32 " \
    "{%0,%1,%2,%3},{%4,%5,%6,%7},{%8,%9},{%0,%1,%2,%3};" \
    : "+f"((c)[0]), "+f"((c)[1]), "+f"((c)[2]), "+f"((c)[3]) \
    : "r"((a)[0]), "r"((a)[1]), "r"((a)[2]), "r"((a)[3]), "r"((b)[0]), "r"((b)[1]))

// ---------------------------------------------------------------------------
// prep 1: Weff = conv weight composed with FIR quarter-kernel -> fp16 images
// ---------------------------------------------------------------------------
__global__ void prep_weff_kernel(const float* __restrict__ weight) {
    int oc = blockIdx.x;
    int c  = threadIdx.x;
    const float kq[4] = {0.25f, 0.75f, 0.75f, 0.25f};

    float w[3][3];
#pragma unroll
    for (int uh = 0; uh < 3; uh++)
#pragma unroll
        for (int uw = 0; uw < 3; uw++)
            w[uh][uw] = weight[((oc * CIN + c) * 3 + uh) * 3 + uw];

    float Keff[6][6];
#pragma unroll
    for (int a = 0; a < 6; a++)
#pragma unroll
        for (int b = 0; b < 6; b++) Keff[a][b] = 0.0f;
#pragma unroll
    for (int uh = 0; uh < 3; uh++)
#pragma unroll
        for (int uw = 0; uw < 3; uw++) {
            float wv = w[uh][uw];
#pragma unroll
            for (int vh = 0; vh < 4; vh++)
#pragma unroll
                for (int vw = 0; vw < 4; vw++)
                    Keff[uh + vh][uw + vw] += wv * kq[vh] * kq[vw];
        }

    int half = oc >> 7, m = oc & 127;
    int kin = c & 63;
#pragma unroll
    for (int p = 0; p < 4; p++) {
        int ph = p >> 1, pw = p & 1;
#pragma unroll
        for (int th = 0; th < 3; th++)
#pragma unroll
            for (int tw = 0; tw < 3; tw++) {
                float v = Keff[2 * th + 1 - ph][2 * tw + 1 - pw];
                int kc = (th * 3 + tw) * 4 + (c >> 6);
                uint32_t off = (uint32_t)((p * 2 + half) * 36 + kc) * 16384u
                             + (uint32_t)m * 128u + (uint32_t)kin * 2u;
                *(__half*)(g_W + off) = __float2half_rn(v);
            }
    }
}

// ---------------------------------------------------------------------------
// prep 2: x fp32 -> c8-packed fp16 16B entries
// ---------------------------------------------------------------------------
__global__ void prep_x8_kernel(const float* __restrict__ x) {
    int idx = blockIdx.x * blockDim.x + threadIdx.x;   // 0 .. 8*32*4096-1
    int hw = idx & 4095;
    int c8 = (idx >> 12) & 31;
    int n  = idx >> 17;
    const float* px = x + ((size_t)n * CIN + c8 * 8) * 4096 + hw;
    ushort h[8];
#pragma unroll
    for (int i = 0; i < 8; i++)
        h[i] = __half_as_ushort(__float2half_rn(px[i * 4096]));
    uint4 v;
    v.x = (uint32_t)h[0] | ((uint32_t)h[1] << 16);
    v.y = (uint32_t)h[2] | ((uint32_t)h[3] << 16);
    v.z = (uint32_t)h[4] | ((uint32_t)h[5] << 16);
    v.w = (uint32_t)h[6] | ((uint32_t)h[7] << 16);
    g_X8[idx] = v;
}

// ---------------------------------------------------------------------------
// main: grid (256 pos-tiles, 2 oc-halves, 2 ph), 512 threads, 192KB dyn smem
// stage (96KB): A[kcu][256 rows x 64k] @ +kcu*32K (row = pslot*128 + m),
//               B[kcu][128 pos x 64k]  @ +64K + kcu*16K. All SW128 swizzled.
// warp tile: M=64 x N=32. wm = warp&3 (M), wn = warp>>2 (N).
// ---------------------------------------------------------------------------
__global__ __launch_bounds__(512, 1) void conv_mma_kernel(
    const float* __restrict__ bias, float* __restrict__ out)
{
    extern __shared__ char smem[];
    const uint32_t sb = smem_u32(smem);
    const int tid = threadIdx.x;
    const int warp = tid >> 5, lane = tid & 31;

    const int bx = blockIdx.x;
    const int n = bx >> 5, t = bx & 31;
    const int ih0 = (t >> 2) * 8, iw0 = (t & 3) * 16;
    const int ochalf = blockIdx.y;
    const int ph = blockIdx.z;

    const int wm = warp & 3, wn = warp >> 2;

    float acc[4][4][4];
#pragma unroll
    for (int mf = 0; mf < 4; mf++)
#pragma unroll
        for (int nf = 0; nf < 4; nf++)
#pragma unroll
            for (int i = 0; i < 4; i++) acc[mf][nf][i] = 0.0f;

    // --- B prefetch geometry: thread -> one pos, (kcu, c8-half)
    const int posT = tid & 127;
    const int selB = tid >> 7;               // 0..3
    const int kcuB = selB >> 1, hfB = selB & 1;
    const int rBr = posT >> 4, cBw = posT & 15;

    // --- ldmatrix geometry (validated mapping)
    const int rowA0 = wm * 64 + (lane & 7) + ((lane >> 3) & 1) * 8;
    const int kbA = ((lane >> 4) & 1) * 16;
    const int rowB0 = wn * 32 + (lane & 7);
    const int kbB = ((lane >> 3) & 1) * 16;

#define PREFETCH(st, s) do {                                                        \
    uint32_t stg = sb + (uint32_t)(s) * 98304u;                                     \
    /* A: 4 tiles of 16KB, tile = kcu*2 + pslot */                                  \
    _Pragma("unroll")                                                               \
    for (int j = 0; j < 8; j++) {                                                   \
        uint32_t v = (uint32_t)(j * 512 + tid);      /* 0..4095 */                  \
        uint32_t tile = v >> 10, idx = v & 1023;                                    \
        int kcu = tile >> 1, pslot = tile & 1;                                      \
        const unsigned char* src = g_W +                                            \
            (size_t)(((ph * 2 + pslot) * 2 + ochalf) * 36 + (2 * (st) + kcu))       \
            * 16384u + idx * 16u;                                                   \
        CP16(stg + tile * 16384u + swz(idx * 16u), src);                            \
    }                                                                               \
    /* B: per thread 4 CP16 */                                                      \
    {                                                                               \
        int tap = (st) >> 1;                                                        \
        int th = tap / 3, tw = tap - th * 3;                                        \
        int cq = 2 * ((st) & 1) + kcuB;               /* 64-ch quarter 0..3 */      \
        int gh = ih0 + rBr - 1 + th, gw = iw0 + cBw - 1 + tw;                       \
        int inb = ((unsigned)gh < 64u && (unsigned)gw < 64u) ? 16 : 0;              \
        uint32_t gidx = (uint32_t)((n * 32 + cq * 8 + hfB * 4) * 4096)              \
                        + (inb ? (uint32_t)(gh * 64 + gw) : 0u);                    \
        uint32_t brow = stg + 65536u + (uint32_t)kcuB * 16384u;                     \
        uint32_t boff = (uint32_t)posT * 128u + (uint32_t)hfB * 64u;                \
        _Pragma("unroll")                                                           \
        for (int i = 0; i < 4; i++)                                                 \
            CP16Z(brow + swz(boff + (uint32_t)i * 16u),                             \
                  g_X8 + gidx + i * 4096, inb);                                     \
    }                                                                               \
} while (0)

    PREFETCH(0, 0);
    CP_COMMIT();

    for (int st = 0; st < 18; st++) {
        const int s = st & 1;
        if (st + 1 < 18) {
            PREFETCH(st + 1, s ^ 1);
            CP_COMMIT();
            CP_WAIT1();
        } else {
            CP_WAIT0();
        }
        __syncthreads();

        const uint32_t stg = sb + (uint32_t)s * 98304u;

#pragma unroll
        for (int kcu = 0; kcu < 2; kcu++) {
            const uint32_t A0 = stg + (uint32_t)kcu * 32768u;
            const uint32_t B0 = stg + 65536u + (uint32_t)kcu * 16384u;
#pragma unroll
            for (int ks = 0; ks < 4; ks++) {
                uint32_t a[4][4], b[4][2];
#pragma unroll
                for (int mf = 0; mf < 4; mf++) {
                    uint32_t ao = swz((uint32_t)(rowA0 + mf * 16) * 128u
                                      + (uint32_t)(ks * 32 + kbA));
                    LDSM4(a[mf], A0 + ao);
                }
#pragma unroll
                for (int nf = 0; nf < 4; nf++) {
                    uint32_t bo = swz((uint32_t)(rowB0 + nf * 8) * 128u
                                      + (uint32_t)(ks * 32 + kbB));
                    LDSM2(b[nf], B0 + bo);
                }
#pragma unroll
                for (int mf = 0; mf < 4; mf++)
#pragma unroll
                    for (int nf = 0; nf < 4; nf++)
                        MMA(acc[mf][nf], a[mf], b[nf]);
            }
        }
        __syncthreads();
    }

    // ---- epilogue: two passes over oc-quarters; ep[pslot][ocq 0..63][pos 128]
    float* ep = (float*)smem;                     // pitch 130 floats
    const int g = lane >> 2, tq = lane & 3;
    const int ocq_t = tid >> 3, r_t = tid & 7;

#pragma unroll
    for (int q = 0; q < 2; q++) {
        __syncthreads();
        if ((wm & 1) == q) {
            int pslot = wm >> 1;
#pragma unroll
            for (int mf = 0; mf < 4; mf++) {
                int ocq = mf * 16 + g;
#pragma unroll
                for (int nf = 0; nf < 4; nf++) {
                    int col = wn * 32 + nf * 8 + tq * 2;
                    float* e = ep + (pslot * 64 + ocq) * 130 + col;
                    *(float2*)e             = make_float2(acc[mf][nf][0], acc[mf][nf][1]);
                    *(float2*)(e + 8 * 130) = make_float2(acc[mf][nf][2], acc[mf][nf][3]);
                }
            }
        }
        __syncthreads();

        int oc = ochalf * 128 + q * 64 + ocq_t;
        float bv = bias[oc];
        const float* e0 = ep + ocq_t * 130 + r_t * 16;
        const float* e1 = e0 + 64 * 130;
        float4* dst = (float4*)(out + (((size_t)n * OCH + oc) * 128
                        + 2 * (ih0 + r_t) + ph) * 128 + 2 * iw0);
#pragma unroll
        for (int k = 0; k < 8; k++) {
            float4 v;
            v.x = e0[2 * k] + bv;
            v.y = e1[2 * k] + bv;
            v.z = e0[2 * k + 1] + bv;
            v.w = e1[2 * k + 1] + bv;
            dst[k] = v;
        }
    }
}

extern "C" void kernel_launch(void* const* d_in, const int* in_sizes, int n_in,
                              void* d_out, int out_size) {
    const float* hidden = (const float*)d_in[0];   // (8,256,64,64)
    const float* weight = (const float*)d_in[1];   // (256,256,3,3)
    const float* bias   = (const float*)d_in[2];   // (256,)
    float* out = (float*)d_out;                    // (8,256,128,128)

    cudaFuncSetAttribute(conv_mma_kernel,
                         cudaFuncAttributeMaxDynamicSharedMemorySize, 196608);

    prep_weff_kernel<<<256, 256>>>(weight);
    prep_x8_kernel<<<2048, 512>>>(hidden);
    conv_mma_kernel<<<dim3(256, 2, 2), 512, 196608>>>(bias, out);
}

// round 7
// speedup vs baseline: 4.5420x; 1.6426x over previous
#include <cuda_runtime.h>
#include <cuda_fp16.h>
#include <cstdint>

// ============================================================================
// FirUpsample2D, two-stage minimal-FLOP formulation.
// Stage 1 (tensor): y = convT(x, w, up=2, pad=2) computed as 4 parity-plane
//   convs: plane (ry,rx) has taps u = {0,2} if ry==0 else {1} (same for v),
//   K = ntaps*256. y planes stored fp32 flat [n][plane][oc][pos].
//     p0 (ee): 65x65, K=1024   p1 (eo): 65x64, K=512
//     p2 (oe): 64x65, K=512    p3 (oo): 64x64, K=256
// Stage 2 (memory): out[2m+ph][2k+pw] = bias + sum of 2x2-ish neighborhoods of
//   the 4 planes with separable weights [.25,.75]/[.75,.25] per dim.
// ============================================================================

#define CIN 256
#define OCH 256

// fp16 weight images: [plane][octile][kc<=16][128 rows x 64 k]  (2 MB)
__device__ __align__(16) __half g_W2[4 * 2 * 16 * 8192];
// fp16 input, c8-packed: uint4[(n*32+c8)*4096 + h*64 + w] = ch 8c8..8c8+7
__device__ __align__(16) uint4 g_X8[8 * 32 * 4096];
// y planes fp32 flat: [n][plane][oc][4352]
__device__ __align__(16) float g_Y[8 * 4 * 256 * 4352];

__device__ __forceinline__ uint32_t swz(uint32_t o) { return o ^ ((o >> 3) & 0x70); }

__device__ __forceinline__ uint32_t smem_u32(const void* p) {
    uint32_t a;
    asm("{ .reg .u64 t; cvta.to.shared.u64 t, %1; cvt.u32.u64 %0, t; }" : "=r"(a) : "l"(p));
    return a;
}

#define CP16(d, s) asm volatile("cp.async.cg.shared.global [%0], [%1], 16;" :: "r"(d), "l"(s) : "memory")
#define CP16Z(d, s, z) asm volatile("cp.async.cg.shared.global [%0], [%1], 16, %2;" :: "r"(d), "l"(s), "r"(z) : "memory")
#define CP_COMMIT() asm volatile("cp.async.commit_group;" ::: "memory")
#define CP_WAIT1() asm volatile("cp.async.wait_group 1;" ::: "memory")
#define CP_WAIT0() asm volatile("cp.async.wait_group 0;" ::: "memory")

#define LDSM4(r, a) asm volatile( \
    "ldmatrix.sync.aligned.m8n8.x4.shared.b16 {%0,%1,%2,%3}, [%4];" \
    : "=r"((r)[0]), "=r"((r)[1]), "=r"((r)[2]), "=r"((r)[3]) : "r"(a))
#define LDSM2(r, a) asm volatile( \
    "ldmatrix.sync.aligned.m8n8.x2.shared.b16 {%0,%1}, [%2];" \
    : "=r"((r)[0]), "=r"((r)[1]) : "r"(a))

#define MMA(c, a, b) asm volatile( \
    "mma.sync.aligned.m16n8k16.row.col.f32.f16.f16.f32 " \
    "{%0,%1,%2,%3},{%4,%5,%6,%7},{%8,%9},{%0,%1,%2,%3};" \
    : "+f"((c)[0]), "+f"((c)[1]), "+f"((c)[2]), "+f"((c)[3]) \
    : "r"((a)[0]), "r"((a)[1]), "r"((a)[2]), "r"((a)[3]), "r"((b)[0]), "r"((b)[1]))

// ---------------------------------------------------------------------------
// prep 1: raw conv weights -> per-plane fp16 A images
// ---------------------------------------------------------------------------
__global__ void prep_w2_kernel(const float* __restrict__ weight) {
    int oc = blockIdx.x;
    int ch = threadIdx.x;
    float wv[3][3];
#pragma unroll
    for (int u = 0; u < 3; u++)
#pragma unroll
        for (int v = 0; v < 3; v++)
            wv[u][v] = weight[((oc * CIN + ch) * 3 + u) * 3 + v];

    int octile = oc >> 7, row = oc & 127;
    int q = ch >> 6, k = ch & 63;

    auto st = [&](int plane, int t, int u, int v) {
        int kc = t * 4 + q;
        size_t off = ((size_t)((plane * 2 + octile) * 16 + kc)) * 8192
                   + (size_t)row * 64 + k;
        g_W2[off] = __float2half_rn(wv[u][v]);
    };
    // plane ee: t = (du<<1)|dv, (u,v) = (2du, 2dv)
    st(0, 0, 0, 0); st(0, 1, 0, 2); st(0, 2, 2, 0); st(0, 3, 2, 2);
    // plane eo: t = du, (u,v) = (2t, 1)
    st(1, 0, 0, 1); st(1, 1, 2, 1);
    // plane oe: t = dv, (u,v) = (1, 2t)
    st(2, 0, 1, 0); st(2, 1, 1, 2);
    // plane oo
    st(3, 0, 1, 1);
}

// ---------------------------------------------------------------------------
// prep 2: x fp32 -> c8-packed fp16 (unchanged from R6)
// ---------------------------------------------------------------------------
__global__ void prep_x8_kernel(const float* __restrict__ x) {
    int idx = blockIdx.x * blockDim.x + threadIdx.x;
    int hw = idx & 4095;
    int c8 = (idx >> 12) & 31;
    int n  = idx >> 17;
    const float* px = x + ((size_t)n * CIN + c8 * 8) * 4096 + hw;
    ushort h[8];
#pragma unroll
    for (int i = 0; i < 8; i++)
        h[i] = __half_as_ushort(__float2half_rn(px[i * 4096]));
    uint4 v;
    v.x = (uint32_t)h[0] | ((uint32_t)h[1] << 16);
    v.y = (uint32_t)h[2] | ((uint32_t)h[3] << 16);
    v.z = (uint32_t)h[4] | ((uint32_t)h[5] << 16);
    v.w = (uint32_t)h[6] | ((uint32_t)h[7] << 16);
    g_X8[idx] = v;
}

// ---------------------------------------------------------------------------
// Stage 1: grid (34 tiles, 8 n, 4 planes), 512 threads, 192KB smem.
// CTA: M=256 oc x N=128 flat plane positions. K chunks of 64: kc = tap*4+chq.
// Stage of pipeline = 2 chunks (96KB: A 4x16KB, B 2x16KB). Same MMA core as R6.
// ---------------------------------------------------------------------------
__global__ __launch_bounds__(512, 1) void conv_s1_kernel() {
    const int plane = blockIdx.z;
    const int n = blockIdx.y;
    const int tile = blockIdx.x;

    const int R = 65 - (plane >> 1);
    const int C = 65 - (plane & 1);
    const int npos = R * C;
    if (tile * 128 >= npos) return;
    const int nst = (plane == 0) ? 8 : ((plane == 3) ? 2 : 4);

    extern __shared__ char smem[];
    const uint32_t sb = smem_u32(smem);
    const int tid = threadIdx.x;
    const int warp = tid >> 5, lane = tid & 31;
    const int wm = warp & 3, wn = warp >> 2;

    float acc[4][4][4];
#pragma unroll
    for (int mf = 0; mf < 4; mf++)
#pragma unroll
        for (int nf = 0; nf < 4; nf++)
#pragma unroll
            for (int i = 0; i < 4; i++) acc[mf][nf][i] = 0.0f;

    // B prefetch geometry
    const int posT = tid & 127;
    const int selB = tid >> 7;
    const int kcuB = selB >> 1, hfB = selB & 1;
    const int pos = tile * 128 + posT;
    int bT, cT;
    if ((plane & 1) == 0) { bT = (int)(((unsigned)pos * 16133u) >> 20); cT = pos - bT * 65; }
    else                  { bT = pos >> 6; cT = pos & 63; }
    const int posOK = pos < npos;

    // ldmatrix geometry (validated R6 mapping)
    const int rowA0 = wm * 64 + (lane & 7) + ((lane >> 3) & 1) * 8;
    const int kbA = ((lane >> 4) & 1) * 16;
    const int rowB0 = wn * 32 + (lane & 7);
    const int kbB = ((lane >> 3) & 1) * 16;

#define PREFETCH(st, s) do {                                                        \
    uint32_t stg = sb + (uint32_t)(s) * 98304u;                                     \
    _Pragma("unroll")                                                               \
    for (int j = 0; j < 8; j++) {                                                   \
        uint32_t v = (uint32_t)(j * 512 + tid);                                     \
        uint32_t tile4 = v >> 10, idx = v & 1023;                                   \
        int kcu = tile4 >> 1, octile = tile4 & 1;                                   \
        const unsigned char* src = (const unsigned char*)g_W2                       \
            + ((size_t)((plane * 2 + octile) * 16 + (2 * (st) + kcu))) * 16384u     \
            + idx * 16u;                                                            \
        CP16(stg + tile4 * 16384u + swz(idx * 16u), src);                           \
    }                                                                               \
    {                                                                               \
        int kc = 2 * (st) + kcuB;                                                   \
        int t = kc >> 2, q = kc & 3;                                                \
        int gh, gw;                                                                 \
        if (plane == 0)      { gh = bT - 1 + (t >> 1); gw = cT - 1 + (t & 1); }     \
        else if (plane == 1) { gh = bT - 1 + t;        gw = cT; }                   \
        else if (plane == 2) { gh = bT;                gw = cT - 1 + t; }           \
        else                 { gh = bT;                gw = cT; }                   \
        int inb = ((unsigned)gh < 64u && (unsigned)gw < 64u && posOK) ? 16 : 0;     \
        uint32_t gidx = (uint32_t)((n * 32 + q * 8 + hfB * 4) * 4096)               \
                        + (inb ? (uint32_t)(gh * 64 + gw) : 0u);                    \
        uint32_t brow = stg + 65536u + (uint32_t)kcuB * 16384u;                     \
        uint32_t boff = (uint32_t)posT * 128u + (uint32_t)hfB * 64u;                \
        _Pragma("unroll")                                                           \
        for (int i = 0; i < 4; i++)                                                 \
            CP16Z(brow + swz(boff + (uint32_t)i * 16u),                             \
                  g_X8 + gidx + i * 4096, inb);                                     \
    }                                                                               \
} while (0)

    PREFETCH(0, 0);
    CP_COMMIT();

    for (int st = 0; st < nst; st++) {
        const int s = st & 1;
        if (st + 1 < nst) {
            PREFETCH(st + 1, s ^ 1);
            CP_COMMIT();
            CP_WAIT1();
        } else {
            CP_WAIT0();
        }
        __syncthreads();

        const uint32_t stg = sb + (uint32_t)s * 98304u;
#pragma unroll
        for (int kcu = 0; kcu < 2; kcu++) {
            const uint32_t A0 = stg + (uint32_t)kcu * 32768u;
            const uint32_t B0 = stg + 65536u + (uint32_t)kcu * 16384u;
#pragma unroll
            for (int ks = 0; ks < 4; ks++) {
                uint32_t a[4][4], b[4][2];
#pragma unroll
                for (int mf = 0; mf < 4; mf++) {
                    uint32_t ao = swz((uint32_t)(rowA0 + mf * 16) * 128u
                                      + (uint32_t)(ks * 32 + kbA));
                    LDSM4(a[mf], A0 + ao);
                }
#pragma unroll
                for (int nf = 0; nf < 4; nf++) {
                    uint32_t bo = swz((uint32_t)(rowB0 + nf * 8) * 128u
                                      + (uint32_t)(ks * 32 + kbB));
                    LDSM2(b[nf], B0 + bo);
                }
#pragma unroll
                for (int mf = 0; mf < 4; mf++)
#pragma unroll
                    for (int nf = 0; nf < 4; nf++)
                        MMA(acc[mf][nf], a[mf], b[nf]);
            }
        }
        __syncthreads();
    }

    // ---- epilogue: write fp32 y, coalesced flat [oc][pos]
    const int g = lane >> 2, tq = lane & 3;
    float* ybase = g_Y + (size_t)(n * 4 + plane) * 256 * 4352;
#pragma unroll
    for (int mf = 0; mf < 4; mf++) {
#pragma unroll
        for (int nf = 0; nf < 4; nf++) {
            int pos0 = tile * 128 + wn * 32 + nf * 8 + tq * 2;
            int oc0 = wm * 64 + mf * 16 + g;
            float* y0 = ybase + (size_t)oc0 * 4352 + pos0;
            float* y1 = ybase + (size_t)(oc0 + 8) * 4352 + pos0;
            if (pos0 + 1 < npos) {
                *(float2*)y0 = make_float2(acc[mf][nf][0], acc[mf][nf][1]);
                *(float2*)y1 = make_float2(acc[mf][nf][2], acc[mf][nf][3]);
            } else if (pos0 < npos) {
                *y0 = acc[mf][nf][0];
                *y1 = acc[mf][nf][2];
            }
        }
    }
}

// ---------------------------------------------------------------------------
// Stage 2: FIR parity blend + bias. grid (256 oc, 8 n), 256 threads, 74KB smem.
// smem: 4 planes, each 68x68 fp32 with zero halo; plane index offset +1.
// ---------------------------------------------------------------------------
__global__ __launch_bounds__(256) void blur_kernel(
    const float* __restrict__ bias, float* __restrict__ out)
{
    extern __shared__ float sm[];          // 4 * 4624 floats
    const int tid = threadIdx.x;
    const int oc = blockIdx.x, n = blockIdx.y;

    // zero all (halo included)
    float4 z = make_float4(0.f, 0.f, 0.f, 0.f);
    for (int i = tid; i < 4624; i += 256) ((float4*)sm)[i] = z;
    __syncthreads();

    // fill interiors from flat y
#pragma unroll
    for (int p = 0; p < 4; p++) {
        int C = 65 - (p & 1), R = 65 - (p >> 1), np = R * C;
        const float* src = g_Y + ((size_t)(n * 4 + p) * 256 + oc) * 4352;
        float* dst = sm + p * 4624;
        for (int i = tid; i < np; i += 256) {
            int b, c;
            if ((p & 1) == 0) { b = (int)(((unsigned)i * 16133u) >> 20); c = i - b * 65; }
            else              { b = i >> 6; c = i & 63; }
            dst[(b + 1) * 68 + (c + 1)] = src[i];
        }
    }
    __syncthreads();

    const float bv = bias[oc];
    const float* EEp = sm;
    const float* EOp = sm + 4624;
    const float* OEp = sm + 9248;
    const float* OOp = sm + 13872;
    float* obase = out + (size_t)(n * 256 + oc) * 16384;

    const float A = 0.25f, B = 0.75f;
#pragma unroll 4
    for (int it = 0; it < 16; it++) {
        int id = it * 256 + tid;
        int m = id >> 6, k = id & 63;
        const float* ee = EEp + (m + 1) * 68 + (k + 1);
        const float* eo = EOp + (m + 1) * 68 + k;
        const float* oe = OEp + m * 68 + (k + 1);
        const float* oo = OOp + m * 68 + k;

        float rowE[2][2], rowO[3][2];
#pragma unroll
        for (int i = 0; i < 2; i++) {
            float e0 = ee[i * 68], e1 = ee[i * 68 + 1];
            float f0 = eo[i * 68], f1 = eo[i * 68 + 1], f2 = eo[i * 68 + 2];
            rowE[i][0] = B * e0 + A * e1 + A * f0 + B * f1;
            rowE[i][1] = A * e0 + B * e1 + B * f1 + A * f2;
        }
#pragma unroll
        for (int i = 0; i < 3; i++) {
            float e0 = oe[i * 68], e1 = oe[i * 68 + 1];
            float f0 = oo[i * 68], f1 = oo[i * 68 + 1], f2 = oo[i * 68 + 2];
            rowO[i][0] = B * e0 + A * e1 + A * f0 + B * f1;
            rowO[i][1] = A * e0 + B * e1 + B * f1 + A * f2;
        }
        float o00 = B * rowE[0][0] + A * rowE[1][0] + A * rowO[0][0] + B * rowO[1][0] + bv;
        float o01 = B * rowE[0][1] + A * rowE[1][1] + A * rowO[0][1] + B * rowO[1][1] + bv;
        float o10 = A * rowE[0][0] + B * rowE[1][0] + B * rowO[1][0] + A * rowO[2][0] + bv;
        float o11 = A * rowE[0][1] + B * rowE[1][1] + B * rowO[1][1] + A * rowO[2][1] + bv;

        *(float2*)(obase + (2 * m) * 128 + 2 * k)     = make_float2(o00, o01);
        *(float2*)(obase + (2 * m + 1) * 128 + 2 * k) = make_float2(o10, o11);
    }
}

extern "C" void kernel_launch(void* const* d_in, const int* in_sizes, int n_in,
                              void* d_out, int out_size) {
    const float* hidden = (const float*)d_in[0];   // (8,256,64,64)
    const float* weight = (const float*)d_in[1];   // (256,256,3,3)
    const float* bias   = (const float*)d_in[2];   // (256,)
    float* out = (float*)d_out;                    // (8,256,128,128)

    cudaFuncSetAttribute(conv_s1_kernel,
                         cudaFuncAttributeMaxDynamicSharedMemorySize, 196608);
    cudaFuncSetAttribute(blur_kernel,
                         cudaFuncAttributeMaxDynamicSharedMemorySize, 73984);

    prep_w2_kernel<<<256, 256>>>(weight);
    prep_x8_kernel<<<2048, 512>>>(hidden);
    conv_s1_kernel<<<dim3(34, 8, 4), 512, 196608>>>();
    blur_kernel<<<dim3(256, 8), 256, 73984>>>(bias, out);
}

// round 9
// speedup vs baseline: 5.8175x; 1.2808x over previous
#include <cuda_runtime.h>
#include <cuda_fp16.h>
#include <cstdint>

// ============================================================================
// FirUpsample2D, two-stage minimal-FLOP formulation.
// Stage 1 (tensor): y = convT(x, w, up=2, pad=2) as 4 parity-plane convs
//   (K = ntaps*256), y written fp32 into HALO-PADDED planes:
//   g_Yp[n][plane][oc][68 rows x 72 pitch], interior cell (b,c) at (b+1, c+2).
//   Halo is never written; __device__ globals are zero-initialized -> zeros.
// Stage 2 (memory): parity blend [.25,.75] x [.25,.75] + bias, direct global
//   reads (no smem), formulas identical to validated R7 version.
// ============================================================================

#define CIN 256
#define OCH 256

// fp16 weight images: [plane][octile][kc<=16][128 rows x 64 k]  (2 MB)
__device__ __align__(16) __half g_W2[4 * 2 * 16 * 8192];
// fp16 input, c8-packed: uint4[(n*32+c8)*4096 + h*64 + w] = ch 8c8..8c8+7
__device__ __align__(16) uint4 g_X8[8 * 32 * 4096];
// y planes fp32 padded: [n][plane][oc][68*72]  (halo zero from static init)
__device__ __align__(16) float g_Yp[8 * 4 * 256 * 4896];

__device__ __forceinline__ uint32_t swz(uint32_t o) { return o ^ ((o >> 3) & 0x70); }

__device__ __forceinline__ uint32_t smem_u32(const void* p) {
    uint32_t a;
    asm("{ .reg .u64 t; cvta.to.shared.u64 t, %1; cvt.u32.u64 %0, t; }" : "=r"(a) : "l"(p));
    return a;
}

#define CP16(d, s) asm volatile("cp.async.cg.shared.global [%0], [%1], 16;" :: "r"(d), "l"(s) : "memory")
#define CP16Z(d, s, z) asm volatile("cp.async.cg.shared.global [%0], [%1], 16, %2;" :: "r"(d), "l"(s), "r"(z) : "memory")
#define CP_COMMIT() asm volatile("cp.async.commit_group;" ::: "memory")
#define CP_WAIT1() asm volatile("cp.async.wait_group 1;" ::: "memory")
#define CP_WAIT0() asm volatile("cp.async.wait_group 0;" ::: "memory")

#define LDSM4(r, a) asm volatile( \
    "ldmatrix.sync.aligned.m8n8.x4.shared.b16 {%0,%1,%2,%3}, [%4];" \
    : "=r"((r)[0]), "=r"((r)[1]), "=r"((r)[2]), "=r"((r)[3]) : "r"(a))
#define LDSM2(r, a) asm volatile( \
    "ldmatrix.sync.aligned.m8n8.x2.shared.b16 {%0,%1}, [%2];" \
    : "=r"((r)[0]), "=r"((r)[1]) : "r"(a))

#define MMA(c, a, b) asm volatile( \
    "mma.sync.aligned.m16n8k16.row.col.f32.f16.f16.f32 " \
    "{%0,%1,%2,%3},{%4,%5,%6,%7},{%8,%9},{%0,%1,%2,%3};" \
    : "+f"((c)[0]), "+f"((c)[1]), "+f"((c)[2]), "+f"((c)[3]) \
    : "r"((a)[0]), "r"((a)[1]), "r"((a)[2]), "r"((a)[3]), "r"((b)[0]), "r"((b)[1]))

// ---------------------------------------------------------------------------
// prep 1: raw conv weights -> per-plane fp16 A images
// ---------------------------------------------------------------------------
__global__ void prep_w2_kernel(const float* __restrict__ weight) {
    int oc = blockIdx.x;
    int ch = threadIdx.x;
    float wv[3][3];
#pragma unroll
    for (int u = 0; u < 3; u++)
#pragma unroll
        for (int v = 0; v < 3; v++)
            wv[u][v] = weight[((oc * CIN + ch) * 3 + u) * 3 + v];

    int octile = oc >> 7, row = oc & 127;
    int q = ch >> 6, k = ch & 63;

    auto st = [&](int plane, int t, int u, int v) {
        int kc = t * 4 + q;
        size_t off = ((size_t)((plane * 2 + octile) * 16 + kc)) * 8192
                   + (size_t)row * 64 + k;
        g_W2[off] = __float2half_rn(wv[u][v]);
    };
    st(0, 0, 0, 0); st(0, 1, 0, 2); st(0, 2, 2, 0); st(0, 3, 2, 2);
    st(1, 0, 0, 1); st(1, 1, 2, 1);
    st(2, 0, 1, 0); st(2, 1, 1, 2);
    st(3, 0, 1, 1);
}

// ---------------------------------------------------------------------------
// prep 2: x fp32 -> c8-packed fp16
// ---------------------------------------------------------------------------
__global__ void prep_x8_kernel(const float* __restrict__ x) {
    int idx = blockIdx.x * blockDim.x + threadIdx.x;
    int hw = idx & 4095;
    int c8 = (idx >> 12) & 31;
    int n  = idx >> 17;
    const float* px = x + ((size_t)n * CIN + c8 * 8) * 4096 + hw;
    ushort h[8];
#pragma unroll
    for (int i = 0; i < 8; i++)
        h[i] = __half_as_ushort(__float2half_rn(px[i * 4096]));
    uint4 v;
    v.x = (uint32_t)h[0] | ((uint32_t)h[1] << 16);
    v.y = (uint32_t)h[2] | ((uint32_t)h[3] << 16);
    v.z = (uint32_t)h[4] | ((uint32_t)h[5] << 16);
    v.w = (uint32_t)h[6] | ((uint32_t)h[7] << 16);
    g_X8[idx] = v;
}

// ---------------------------------------------------------------------------
// Stage 1: grid (34 tiles, 8 n, 4 planes), 512 threads, 192KB smem.
// CTA: M=256 oc x N=128 flat plane positions. MMA core validated (R6/R7).
// ---------------------------------------------------------------------------
__global__ __launch_bounds__(512, 1) void conv_s1_kernel() {
    const int plane = blockIdx.z;
    const int n = blockIdx.y;
    const int tile = blockIdx.x;

    const int R = 65 - (plane >> 1);
    const int C = 65 - (plane & 1);
    const int npos = R * C;
    if (tile * 128 >= npos) return;
    const int nst = (plane == 0) ? 8 : ((plane == 3) ? 2 : 4);

    extern __shared__ char smem[];
    const uint32_t sb = smem_u32(smem);
    const int tid = threadIdx.x;
    const int warp = tid >> 5, lane = tid & 31;
    const int wm = warp & 3, wn = warp >> 2;

    float acc[4][4][4];
#pragma unroll
    for (int mf = 0; mf < 4; mf++)
#pragma unroll
        for (int nf = 0; nf < 4; nf++)
#pragma unroll
            for (int i = 0; i < 4; i++) acc[mf][nf][i] = 0.0f;

    // B prefetch geometry
    const int posT = tid & 127;
    const int selB = tid >> 7;
    const int kcuB = selB >> 1, hfB = selB & 1;
    const int pos = tile * 128 + posT;
    int bT, cT;
    if ((plane & 1) == 0) { bT = (int)(((unsigned)pos * 16133u) >> 20); cT = pos - bT * 65; }
    else                  { bT = pos >> 6; cT = pos & 63; }
    const int posOK = pos < npos;

    // ldmatrix geometry (validated mapping)
    const int rowA0 = wm * 64 + (lane & 7) + ((lane >> 3) & 1) * 8;
    const int kbA = ((lane >> 4) & 1) * 16;
    const int rowB0 = wn * 32 + (lane & 7);
    const int kbB = ((lane >> 3) & 1) * 16;

#define PREFETCH(st, s) do {                                                        \
    uint32_t stg = sb + (uint32_t)(s) * 98304u;                                     \
    _Pragma("unroll")                                                               \
    for (int j = 0; j < 8; j++) {                                                   \
        uint32_t v = (uint32_t)(j * 512 + tid);                                     \
        uint32_t tile4 = v >> 10, idx = v & 1023;                                   \
        int kcu = tile4 >> 1, octile = tile4 & 1;                                   \
        const unsigned char* src = (const unsigned char*)g_W2                       \
            + ((size_t)((plane * 2 + octile) * 16 + (2 * (st) + kcu))) * 16384u     \
            + idx * 16u;                                                            \
        CP16(stg + tile4 * 16384u + swz(idx * 16u), src);                           \
    }                                                                               \
    {                                                                               \
        int kc = 2 * (st) + kcuB;                                                   \
        int t = kc >> 2, q = kc & 3;                                                \
        int gh, gw;                                                                 \
        if (plane == 0)      { gh = bT - 1 + (t >> 1); gw = cT - 1 + (t & 1); }     \
        else if (plane == 1) { gh = bT - 1 + t;        gw = cT; }                   \
        else if (plane == 2) { gh = bT;                gw = cT - 1 + t; }           \
        else                 { gh = bT;                gw = cT; }                   \
        int inb = ((unsigned)gh < 64u && (unsigned)gw < 64u && posOK) ? 16 : 0;     \
        uint32_t gidx = (uint32_t)((n * 32 + q * 8 + hfB * 4) * 4096)               \
                        + (inb ? (uint32_t)(gh * 64 + gw) : 0u);                    \
        uint32_t brow = stg + 65536u + (uint32_t)kcuB * 16384u;                     \
        uint32_t boff = (uint32_t)posT * 128u + (uint32_t)hfB * 64u;                \
        _Pragma("unroll")                                                           \
        for (int i = 0; i < 4; i++)                                                 \
            CP16Z(brow + swz(boff + (uint32_t)i * 16u),                             \
                  g_X8 + gidx + i * 4096, inb);                                     \
    }                                                                               \
} while (0)

    PREFETCH(0, 0);
    CP_COMMIT();

    for (int st = 0; st < nst; st++) {
        const int s = st & 1;
        if (st + 1 < nst) {
            PREFETCH(st + 1, s ^ 1);
            CP_COMMIT();
            CP_WAIT1();
        } else {
            CP_WAIT0();
        }
        __syncthreads();

        const uint32_t stg = sb + (uint32_t)s * 98304u;
#pragma unroll
        for (int kcu = 0; kcu < 2; kcu++) {
            const uint32_t A0 = stg + (uint32_t)kcu * 32768u;
            const uint32_t B0 = stg + 65536u + (uint32_t)kcu * 16384u;
#pragma unroll
            for (int ks = 0; ks < 4; ks++) {
                uint32_t a[4][4], b[4][2];
#pragma unroll
                for (int mf = 0; mf < 4; mf++) {
                    uint32_t ao = swz((uint32_t)(rowA0 + mf * 16) * 128u
                                      + (uint32_t)(ks * 32 + kbA));
                    LDSM4(a[mf], A0 + ao);
                }
#pragma unroll
                for (int nf = 0; nf < 4; nf++) {
                    uint32_t bo = swz((uint32_t)(rowB0 + nf * 8) * 128u
                                      + (uint32_t)(ks * 32 + kbB));
                    LDSM2(b[nf], B0 + bo);
                }
#pragma unroll
                for (int mf = 0; mf < 4; mf++)
#pragma unroll
                    for (int nf = 0; nf < 4; nf++)
                        MMA(acc[mf][nf], a[mf], b[nf]);
            }
        }
        __syncthreads();
    }

    // ---- epilogue: write fp32 y into padded slices (halo untouched = zero)
    // NOTE: for odd-width planes (C=65) c parity alternates per row, so the
    // 8B-aligned float2 path requires (c & 1) == 0; otherwise scalar stores.
    const int g = lane >> 2, tq = lane & 3;
    float* ybase = g_Yp + (size_t)((n * 4 + plane) * 256) * 4896;
#pragma unroll
    for (int mf = 0; mf < 4; mf++) {
#pragma unroll
        for (int nf = 0; nf < 4; nf++) {
            int pos0 = tile * 128 + wn * 32 + nf * 8 + tq * 2;
            if (pos0 >= npos) continue;
            int oc0 = wm * 64 + mf * 16 + g;
            float* s0 = ybase + (size_t)oc0 * 4896;
            float* s1 = ybase + (size_t)(oc0 + 8) * 4896;
            int b, c;
            if ((plane & 1) == 0) { b = (int)(((unsigned)pos0 * 16133u) >> 20); c = pos0 - b * 65; }
            else                  { b = pos0 >> 6; c = pos0 & 63; }
            uint32_t o0 = (uint32_t)(b + 1) * 72u + (uint32_t)(c + 2);
            bool pair = (pos0 + 1 < npos);
            if (pair && c < C - 1) {
                if ((c & 1) == 0) {
                    *(float2*)(s0 + o0) = make_float2(acc[mf][nf][0], acc[mf][nf][1]);
                    *(float2*)(s1 + o0) = make_float2(acc[mf][nf][2], acc[mf][nf][3]);
                } else {
                    s0[o0] = acc[mf][nf][0]; s0[o0 + 1] = acc[mf][nf][1];
                    s1[o0] = acc[mf][nf][2]; s1[o0 + 1] = acc[mf][nf][3];
                }
            } else {
                s0[o0] = acc[mf][nf][0];
                s1[o0] = acc[mf][nf][2];
                if (pair) {          // row straddle (odd-width plane, c == C-1)
                    uint32_t o1 = (uint32_t)(b + 2) * 72u + 2u;
                    s0[o1] = acc[mf][nf][1];
                    s1[o1] = acc[mf][nf][3];
                }
            }
        }
    }
}

// ---------------------------------------------------------------------------
// Stage 2: FIR parity blend + bias, direct global reads (no smem, no sync).
// grid (256 oc, 8 n, 4 rowgroups), 256 threads; thread -> 2x2 output block.
// ---------------------------------------------------------------------------
__global__ __launch_bounds__(256) void blur_kernel(
    const float* __restrict__ bias, float* __restrict__ out)
{
    const int oc = blockIdx.x, n = blockIdx.y, rg = blockIdx.z;
    const int tid = threadIdx.x;
    const float* EEp = g_Yp + ((size_t)(n * 4 + 0) * 256 + oc) * 4896;
    const float* EOp = g_Yp + ((size_t)(n * 4 + 1) * 256 + oc) * 4896;
    const float* OEp = g_Yp + ((size_t)(n * 4 + 2) * 256 + oc) * 4896;
    const float* OOp = g_Yp + ((size_t)(n * 4 + 3) * 256 + oc) * 4896;
    const float bv = bias[oc];
    float* obase = out + (size_t)(n * 256 + oc) * 16384;

    const float A = 0.25f, B = 0.75f;
#pragma unroll
    for (int it = 0; it < 4; it++) {
        int id = rg * 1024 + it * 256 + tid;
        int m = id >> 6, k = id & 63;
        const float* ee = EEp + (m + 1) * 72 + (k + 2);
        const float* eo = EOp + (m + 1) * 72 + (k + 1);
        const float* oe = OEp + m * 72 + (k + 2);
        const float* oo = OOp + m * 72 + (k + 1);

        float rowE[2][2], rowO[3][2];
#pragma unroll
        for (int i = 0; i < 2; i++) {
            float e0 = ee[i * 72], e1 = ee[i * 72 + 1];
            float f0 = eo[i * 72], f1 = eo[i * 72 + 1], f2 = eo[i * 72 + 2];
            rowE[i][0] = B * e0 + A * e1 + A * f0 + B * f1;
            rowE[i][1] = A * e0 + B * e1 + B * f1 + A * f2;
        }
#pragma unroll
        for (int i = 0; i < 3; i++) {
            float e0 = oe[i * 72], e1 = oe[i * 72 + 1];
            float f0 = oo[i * 72], f1 = oo[i * 72 + 1], f2 = oo[i * 72 + 2];
            rowO[i][0] = B * e0 + A * e1 + A * f0 + B * f1;
            rowO[i][1] = A * e0 + B * e1 + B * f1 + A * f2;
        }
        float o00 = B * rowE[0][0] + A * rowE[1][0] + A * rowO[0][0] + B * rowO[1][0] + bv;
        float o01 = B * rowE[0][1] + A * rowE[1][1] + A * rowO[0][1] + B * rowO[1][1] + bv;
        float o10 = A * rowE[0][0] + B * rowE[1][0] + B * rowO[1][0] + A * rowO[2][0] + bv;
        float o11 = A * rowE[0][1] + B * rowE[1][1] + B * rowO[1][1] + A * rowO[2][1] + bv;

        *(float2*)(obase + (2 * m) * 128 + 2 * k)     = make_float2(o00, o01);
        *(float2*)(obase + (2 * m + 1) * 128 + 2 * k) = make_float2(o10, o11);
    }
}

extern "C" void kernel_launch(void* const* d_in, const int* in_sizes, int n_in,
                              void* d_out, int out_size) {
    const float* hidden = (const float*)d_in[0];   // (8,256,64,64)
    const float* weight = (const float*)d_in[1];   // (256,256,3,3)
    const float* bias   = (const float*)d_in[2];   // (256,)
    float* out = (float*)d_out;                    // (8,256,128,128)

    cudaFuncSetAttribute(conv_s1_kernel,
                         cudaFuncAttributeMaxDynamicSharedMemorySize, 196608);

    prep_w2_kernel<<<256, 256>>>(weight);
    prep_x8_kernel<<<2048, 512>>>(hidden);
    conv_s1_kernel<<<dim3(34, 8, 4), 512, 196608>>>();
    blur_kernel<<<dim3(256, 8, 4), 256>>>(bias, out);
}

// round 11
// speedup vs baseline: 6.6494x; 1.1430x over previous
#include <cuda_runtime.h>
#include <cuda_fp16.h>
#include <cstdint>

// ============================================================================
// FirUpsample2D, two-stage minimal-FLOP formulation.
// Stage 1 (tensor): y = convT(x, w, up=2, pad=2) as 4 parity-plane convs
//   (K = ntaps*256), y written FP16 into HALO-PADDED planes:
//   g_Yp[n][plane][oc][68 rows x 72 pitch], interior cell (b,c) at (b+1, c+2).
//   Halo is never written; __device__ globals are zero-initialized -> zeros.
// Stage 2 (memory): parity blend [.25,.75] x [.25,.75] + bias. Each thread
//   owns TWO adjacent k-columns (k0 even) so all half2 loads are 4B aligned
//   and output is a 16B float4 per row.
// ============================================================================

#define CIN 256
#define OCH 256

// fp16 weight images: [plane][octile][kc<=16][128 rows x 64 k]  (2 MB)
__device__ __align__(16) __half g_W2[4 * 2 * 16 * 8192];
// fp16 input, c8-packed: uint4[(n*32+c8)*4096 + h*64 + w] = ch 8c8..8c8+7
__device__ __align__(16) uint4 g_X8[8 * 32 * 4096];
// y planes fp16 padded: [n][plane][oc][68*72]  (halo zero from static init)
__device__ __align__(16) __half g_Yp[8 * 4 * 256 * 4896];

__device__ __forceinline__ uint32_t swz(uint32_t o) { return o ^ ((o >> 3) & 0x70); }

__device__ __forceinline__ uint32_t smem_u32(const void* p) {
    uint32_t a;
    asm("{ .reg .u64 t; cvta.to.shared.u64 t, %1; cvt.u32.u64 %0, t; }" : "=r"(a) : "l"(p));
    return a;
}

#define CP16(d, s) asm volatile("cp.async.cg.shared.global [%0], [%1], 16;" :: "r"(d), "l"(s) : "memory")
#define CP16Z(d, s, z) asm volatile("cp.async.cg.shared.global [%0], [%1], 16, %2;" :: "r"(d), "l"(s), "r"(z) : "memory")
#define CP_COMMIT() asm volatile("cp.async.commit_group;" ::: "memory")
#define CP_WAIT1() asm volatile("cp.async.wait_group 1;" ::: "memory")
#define CP_WAIT0() asm volatile("cp.async.wait_group 0;" ::: "memory")

#define LDSM4(r, a) asm volatile( \
    "ldmatrix.sync.aligned.m8n8.x4.shared.b16 {%0,%1,%2,%3}, [%4];" \
    : "=r"((r)[0]), "=r"((r)[1]), "=r"((r)[2]), "=r"((r)[3]) : "r"(a))
#define LDSM2(r, a) asm volatile( \
    "ldmatrix.sync.aligned.m8n8.x2.shared.b16 {%0,%1}, [%2];" \
    : "=r"((r)[0]), "=r"((r)[1]) : "r"(a))

#define MMA(c, a, b) asm volatile( \
    "mma.sync.aligned.m16n8k16.row.col.f32.f16.f16.f32 " \
    "{%0,%1,%2,%3},{%4,%5,%6,%7},{%8,%9},{%0,%1,%2,%3};" \
    : "+f"((c)[0]), "+f"((c)[1]), "+f"((c)[2]), "+f"((c)[3]) \
    : "r"((a)[0]), "r"((a)[1]), "r"((a)[2]), "r"((a)[3]), "r"((b)[0]), "r"((b)[1]))

// ---------------------------------------------------------------------------
// prep 1: raw conv weights -> per-plane fp16 A images
// ---------------------------------------------------------------------------
__global__ void prep_w2_kernel(const float* __restrict__ weight) {
    int oc = blockIdx.x;
    int ch = threadIdx.x;
    float wv[3][3];
#pragma unroll
    for (int u = 0; u < 3; u++)
#pragma unroll
        for (int v = 0; v < 3; v++)
            wv[u][v] = weight[((oc * CIN + ch) * 3 + u) * 3 + v];

    int octile = oc >> 7, row = oc & 127;
    int q = ch >> 6, k = ch & 63;

    auto st = [&](int plane, int t, int u, int v) {
        int kc = t * 4 + q;
        size_t off = ((size_t)((plane * 2 + octile) * 16 + kc)) * 8192
                   + (size_t)row * 64 + k;
        g_W2[off] = __float2half_rn(wv[u][v]);
    };
    st(0, 0, 0, 0); st(0, 1, 0, 2); st(0, 2, 2, 0); st(0, 3, 2, 2);
    st(1, 0, 0, 1); st(1, 1, 2, 1);
    st(2, 0, 1, 0); st(2, 1, 1, 2);
    st(3, 0, 1, 1);
}

// ---------------------------------------------------------------------------
// prep 2: x fp32 -> c8-packed fp16
// ---------------------------------------------------------------------------
__global__ void prep_x8_kernel(const float* __restrict__ x) {
    int idx = blockIdx.x * blockDim.x + threadIdx.x;
    int hw = idx & 4095;
    int c8 = (idx >> 12) & 31;
    int n  = idx >> 17;
    const float* px = x + ((size_t)n * CIN + c8 * 8) * 4096 + hw;
    ushort h[8];
#pragma unroll
    for (int i = 0; i < 8; i++)
        h[i] = __half_as_ushort(__float2half_rn(px[i * 4096]));
    uint4 v;
    v.x = (uint32_t)h[0] | ((uint32_t)h[1] << 16);
    v.y = (uint32_t)h[2] | ((uint32_t)h[3] << 16);
    v.z = (uint32_t)h[4] | ((uint32_t)h[5] << 16);
    v.w = (uint32_t)h[6] | ((uint32_t)h[7] << 16);
    g_X8[idx] = v;
}

// ---------------------------------------------------------------------------
// Stage 1: grid (34 tiles, 8 n, 4 planes), 512 threads, 192KB smem.
// CTA: M=256 oc x N=128 flat plane positions. MMA core validated (R6-R9).
// ---------------------------------------------------------------------------
__global__ __launch_bounds__(512, 1) void conv_s1_kernel() {
    const int plane = blockIdx.z;
    const int n = blockIdx.y;
    const int tile = blockIdx.x;

    const int R = 65 - (plane >> 1);
    const int C = 65 - (plane & 1);
    const int npos = R * C;
    if (tile * 128 >= npos) return;
    const int nst = (plane == 0) ? 8 : ((plane == 3) ? 2 : 4);

    extern __shared__ char smem[];
    const uint32_t sb = smem_u32(smem);
    const int tid = threadIdx.x;
    const int warp = tid >> 5, lane = tid & 31;
    const int wm = warp & 3, wn = warp >> 2;

    float acc[4][4][4];
#pragma unroll
    for (int mf = 0; mf < 4; mf++)
#pragma unroll
        for (int nf = 0; nf < 4; nf++)
#pragma unroll
            for (int i = 0; i < 4; i++) acc[mf][nf][i] = 0.0f;

    // B prefetch geometry
    const int posT = tid & 127;
    const int selB = tid >> 7;
    const int kcuB = selB >> 1, hfB = selB & 1;
    const int pos = tile * 128 + posT;
    int bT, cT;
    if ((plane & 1) == 0) { bT = (int)(((unsigned)pos * 16133u) >> 20); cT = pos - bT * 65; }
    else                  { bT = pos >> 6; cT = pos & 63; }
    const int posOK = pos < npos;

    // ldmatrix geometry (validated mapping)
    const int rowA0 = wm * 64 + (lane & 7) + ((lane >> 3) & 1) * 8;
    const int kbA = ((lane >> 4) & 1) * 16;
    const int rowB0 = wn * 32 + (lane & 7);
    const int kbB = ((lane >> 3) & 1) * 16;

#define PREFETCH(st, s) do {                                                        \
    uint32_t stg = sb + (uint32_t)(s) * 98304u;                                     \
    _Pragma("unroll")                                                               \
    for (int j = 0; j < 8; j++) {                                                   \
        uint32_t v = (uint32_t)(j * 512 + tid);                                     \
        uint32_t tile4 = v >> 10, idx = v & 1023;                                   \
        int kcu = tile4 >> 1, octile = tile4 & 1;                                   \
        const unsigned char* src = (const unsigned char*)g_W2                       \
            + ((size_t)((plane * 2 + octile) * 16 + (2 * (st) + kcu))) * 16384u     \
            + idx * 16u;                                                            \
        CP16(stg + tile4 * 16384u + swz(idx * 16u), src);                           \
    }                                                                               \
    {                                                                               \
        int kc = 2 * (st) + kcuB;                                                   \
        int t = kc >> 2, q = kc & 3;                                                \
        int gh, gw;                                                                 \
        if (plane == 0)      { gh = bT - 1 + (t >> 1); gw = cT - 1 + (t & 1); }     \
        else if (plane == 1) { gh = bT - 1 + t;        gw = cT; }                   \
        else if (plane == 2) { gh = bT;                gw = cT - 1 + t; }           \
        else                 { gh = bT;                gw = cT; }                   \
        int inb = ((unsigned)gh < 64u && (unsigned)gw < 64u && posOK) ? 16 : 0;     \
        uint32_t gidx = (uint32_t)((n * 32 + q * 8 + hfB * 4) * 4096)               \
                        + (inb ? (uint32_t)(gh * 64 + gw) : 0u);                    \
        uint32_t brow = stg + 65536u + (uint32_t)kcuB * 16384u;                     \
        uint32_t boff = (uint32_t)posT * 128u + (uint32_t)hfB * 64u;                \
        _Pragma("unroll")                                                           \
        for (int i = 0; i < 4; i++)                                                 \
            CP16Z(brow + swz(boff + (uint32_t)i * 16u),                             \
                  g_X8 + gidx + i * 4096, inb);                                     \
    }                                                                               \
} while (0)

    PREFETCH(0, 0);
    CP_COMMIT();

    for (int st = 0; st < nst; st++) {
        const int s = st & 1;
        if (st + 1 < nst) {
            PREFETCH(st + 1, s ^ 1);
            CP_COMMIT();
            CP_WAIT1();
        } else {
            CP_WAIT0();
        }
        __syncthreads();

        const uint32_t stg = sb + (uint32_t)s * 98304u;
#pragma unroll
        for (int kcu = 0; kcu < 2; kcu++) {
            const uint32_t A0 = stg + (uint32_t)kcu * 32768u;
            const uint32_t B0 = stg + 65536u + (uint32_t)kcu * 16384u;
#pragma unroll
            for (int ks = 0; ks < 4; ks++) {
                uint32_t a[4][4], b[4][2];
#pragma unroll
                for (int mf = 0; mf < 4; mf++) {
                    uint32_t ao = swz((uint32_t)(rowA0 + mf * 16) * 128u
                                      + (uint32_t)(ks * 32 + kbA));
                    LDSM4(a[mf], A0 + ao);
                }
#pragma unroll
                for (int nf = 0; nf < 4; nf++) {
                    uint32_t bo = swz((uint32_t)(rowB0 + nf * 8) * 128u
                                      + (uint32_t)(ks * 32 + kbB));
                    LDSM2(b[nf], B0 + bo);
                }
#pragma unroll
                for (int mf = 0; mf < 4; mf++)
#pragma unroll
                    for (int nf = 0; nf < 4; nf++)
                        MMA(acc[mf][nf], a[mf], b[nf]);
            }
        }
        __syncthreads();
    }

    // ---- epilogue: write fp16 y into padded slices (halo untouched = zero)
    // half2 (4B) store requires even half-offset => (c & 1) == 0 path only.
    const int g = lane >> 2, tq = lane & 3;
    __half* ybase = g_Yp + (size_t)((n * 4 + plane) * 256) * 4896;
#pragma unroll
    for (int mf = 0; mf < 4; mf++) {
#pragma unroll
        for (int nf = 0; nf < 4; nf++) {
            int pos0 = tile * 128 + wn * 32 + nf * 8 + tq * 2;
            if (pos0 >= npos) continue;
            int oc0 = wm * 64 + mf * 16 + g;
            __half* s0 = ybase + (size_t)oc0 * 4896;
            __half* s1 = ybase + (size_t)(oc0 + 8) * 4896;
            int b, c;
            if ((plane & 1) == 0) { b = (int)(((unsigned)pos0 * 16133u) >> 20); c = pos0 - b * 65; }
            else                  { b = pos0 >> 6; c = pos0 & 63; }
            uint32_t o0 = (uint32_t)(b + 1) * 72u + (uint32_t)(c + 2);
            bool pair = (pos0 + 1 < npos);
            __half h0 = __float2half_rn(acc[mf][nf][0]);
            __half h1 = __float2half_rn(acc[mf][nf][1]);
            __half h2 = __float2half_rn(acc[mf][nf][2]);
            __half h3 = __float2half_rn(acc[mf][nf][3]);
            if (pair && c < C - 1) {
                if ((c & 1) == 0) {
                    *(__half2*)(s0 + o0) = __halves2half2(h0, h1);
                    *(__half2*)(s1 + o0) = __halves2half2(h2, h3);
                } else {
                    s0[o0] = h0; s0[o0 + 1] = h1;
                    s1[o0] = h2; s1[o0 + 1] = h3;
                }
            } else {
                s0[o0] = h0;
                s1[o0] = h2;
                if (pair) {          // row straddle (odd-width plane, c == C-1)
                    uint32_t o1 = (uint32_t)(b + 2) * 72u + 2u;
                    s0[o1] = h1;
                    s1[o1] = h3;
                }
            }
        }
    }
}

// ---------------------------------------------------------------------------
// Stage 2: FIR parity blend + bias. Thread -> 2 rows x 4 cols output block
// (column pair k0=2*kp, so ALL half2 loads sit at even half offsets).
// grid (256 oc, 8 n, 4 rowgroups), 256 threads, 2 iters.
// ---------------------------------------------------------------------------
__global__ __launch_bounds__(256) void blur_kernel(
    const float* __restrict__ bias, float* __restrict__ out)
{
    const int oc = blockIdx.x, n = blockIdx.y, rg = blockIdx.z;
    const int tid = threadIdx.x;
    const __half* EEp = g_Yp + ((size_t)(n * 4 + 0) * 256 + oc) * 4896;
    const __half* EOp = g_Yp + ((size_t)(n * 4 + 1) * 256 + oc) * 4896;
    const __half* OEp = g_Yp + ((size_t)(n * 4 + 2) * 256 + oc) * 4896;
    const __half* OOp = g_Yp + ((size_t)(n * 4 + 3) * 256 + oc) * 4896;
    const float bv = bias[oc];
    float* obase = out + (size_t)(n * 256 + oc) * 16384;

    const float A = 0.25f, B = 0.75f;
#pragma unroll
    for (int it = 0; it < 2; it++) {
        int id = rg * 512 + it * 256 + tid;
        int m = id >> 5, kp = id & 31;
        int k0 = kp * 2;                       // even column base

        float rowE[2][4], rowO[3][4];
#pragma unroll
        for (int i = 0; i < 2; i++) {
            const __half2* eeP = (const __half2*)(EEp + (m + 1 + i) * 72 + k0 + 2);
            const __half2* eoP = (const __half2*)(EOp + (m + 1 + i) * 72 + k0);
            float2 a0 = __half22float2(eeP[0]);
            float2 a1 = __half22float2(eeP[1]);
            float2 b0 = __half22float2(eoP[0]);
            float2 b1 = __half22float2(eoP[1]);
            float2 b2 = __half22float2(eoP[2]);
            float e2 = a0.x, e3 = a0.y, e4 = a1.x;
            float f1 = b0.y, f2 = b1.x, f3 = b1.y, f4 = b2.x;
            rowE[i][0] = B * e2 + A * e3 + A * f1 + B * f2;
            rowE[i][1] = A * e2 + B * e3 + B * f2 + A * f3;
            rowE[i][2] = B * e3 + A * e4 + A * f2 + B * f3;
            rowE[i][3] = A * e3 + B * e4 + B * f3 + A * f4;
        }
#pragma unroll
        for (int i = 0; i < 3; i++) {
            const __half2* oeP = (const __half2*)(OEp + (m + i) * 72 + k0 + 2);
            const __half2* ooP = (const __half2*)(OOp + (m + i) * 72 + k0);
            float2 a0 = __half22float2(oeP[0]);
            float2 a1 = __half22float2(oeP[1]);
            float2 b0 = __half22float2(ooP[0]);
            float2 b1 = __half22float2(ooP[1]);
            float2 b2 = __half22float2(ooP[2]);
            float e2 = a0.x, e3 = a0.y, e4 = a1.x;
            float f1 = b0.y, f2 = b1.x, f3 = b1.y, f4 = b2.x;
            rowO[i][0] = B * e2 + A * e3 + A * f1 + B * f2;
            rowO[i][1] = A * e2 + B * e3 + B * f2 + A * f3;
            rowO[i][2] = B * e3 + A * e4 + A * f2 + B * f3;
            rowO[i][3] = A * e3 + B * e4 + B * f3 + A * f4;
        }

        float4 o0, o1;
        o0.x = B * rowE[0][0] + A * rowE[1][0] + A * rowO[0][0] + B * rowO[1][0] + bv;
        o0.y = B * rowE[0][1] + A * rowE[1][1] + A * rowO[0][1] + B * rowO[1][1] + bv;
        o0.z = B * rowE[0][2] + A * rowE[1][2] + A * rowO[0][2] + B * rowO[1][2] + bv;
        o0.w = B * rowE[0][3] + A * rowE[1][3] + A * rowO[0][3] + B * rowO[1][3] + bv;
        o1.x = A * rowE[0][0] + B * rowE[1][0] + B * rowO[1][0] + A * rowO[2][0] + bv;
        o1.y = A * rowE[0][1] + B * rowE[1][1] + B * rowO[1][1] + A * rowO[2][1] + bv;
        o1.z = A * rowE[0][2] + B * rowE[1][2] + B * rowO[1][2] + A * rowO[2][2] + bv;
        o1.w = A * rowE[0][3] + B * rowE[1][3] + B * rowO[1][3] + A * rowO[2][3] + bv;

        *(float4*)(obase + (2 * m) * 128 + 2 * k0)     = o0;
        *(float4*)(obase + (2 * m + 1) * 128 + 2 * k0) = o1;
    }
}

extern "C" void kernel_launch(void* const* d_in, const int* in_sizes, int n_in,
                              void* d_out, int out_size) {
    const float* hidden = (const float*)d_in[0];   // (8,256,64,64)
    const float* weight = (const float*)d_in[1];   // (256,256,3,3)
    const float* bias   = (const float*)d_in[2];   // (256,)
    float* out = (float*)d_out;                    // (8,256,128,128)

    cudaFuncSetAttribute(conv_s1_kernel,
                         cudaFuncAttributeMaxDynamicSharedMemorySize, 196608);

    prep_w2_kernel<<<256, 256>>>(weight);
    prep_x8_kernel<<<2048, 512>>>(hidden);
    conv_s1_kernel<<<dim3(34, 8, 4), 512, 196608>>>();
    blur_kernel<<<dim3(256, 8, 4), 256>>>(bias, out);
}